// round 13
// baseline (speedup 1.0000x reference)
#include <cuda_runtime.h>
#include <cuda_fp16.h>
#include <math.h>

#define BB 64
#define SS 512
#define DD 1024
#define HH 1024
#define GG 4096
#define LOSC 2048.0f
#define ILOSC 0.00048828125f

typedef unsigned int u32;

// ================= helpers =================
__device__ __forceinline__ void cp_async16(unsigned s, const void* g) {
    asm volatile("cp.async.ca.shared.global [%0], [%1], 16;" :: "r"(s), "l"(g));
}
__device__ __forceinline__ void cp_async16_cg(unsigned s, const void* g) {
    asm volatile("cp.async.cg.shared.global [%0], [%1], 16;" :: "r"(s), "l"(g));
}
__device__ __forceinline__ void cp_commit() { asm volatile("cp.async.commit_group;"); }
template<int N> __device__ __forceinline__ void cp_wait() {
    asm volatile("cp.async.wait_group %0;" :: "n"(N));
}
__device__ __forceinline__ u32 smem_u32(const void* p) {
    u32 a;
    asm("{ .reg .u64 t; cvta.to.shared.u64 t, %1; cvt.u32.u64 %0, t; }" : "=r"(a) : "l"(p));
    return a;
}
__device__ __forceinline__ void ldsm_x4(u32 addr, u32& r0, u32& r1, u32& r2, u32& r3) {
    asm volatile("ldmatrix.sync.aligned.m8n8.x4.shared.b16 {%0,%1,%2,%3}, [%4];"
                 : "=r"(r0), "=r"(r1), "=r"(r2), "=r"(r3) : "r"(addr));
}
__device__ __forceinline__ void ldsm_x4t(u32 addr, u32& r0, u32& r1, u32& r2, u32& r3) {
    asm volatile("ldmatrix.sync.aligned.m8n8.x4.trans.shared.b16 {%0,%1,%2,%3}, [%4];"
                 : "=r"(r0), "=r"(r1), "=r"(r2), "=r"(r3) : "r"(addr));
}
__device__ __forceinline__ void mma16816(float* c, u32 a0, u32 a1, u32 a2, u32 a3, u32 b0, u32 b1) {
    asm volatile("mma.sync.aligned.m16n8k16.row.col.f32.f16.f16.f32 "
                 "{%0,%1,%2,%3},{%4,%5,%6,%7},{%8,%9},{%0,%1,%2,%3};"
                 : "+f"(c[0]), "+f"(c[1]), "+f"(c[2]), "+f"(c[3])
                 : "r"(a0), "r"(a1), "r"(a2), "r"(a3), "r"(b0), "r"(b1));
}
__device__ __forceinline__ u32 ld_acq(const u32* p) {
    u32 v;
    asm volatile("ld.acquire.gpu.global.u32 %0, [%1];" : "=r"(v) : "l"(p) : "memory");
    return v;
}
__device__ __forceinline__ void red_release(u32* p) {
    asm volatile("red.release.gpu.global.add.u32 [%0], 1;" :: "l"(p) : "memory");
}
__device__ __forceinline__ float sigf(float x) {
    return __fmaf_rn(0.5f, tanhf(0.5f * x), 0.5f);
}

__host__ __device__ __forceinline__ int gmap(int p) { return (p & 3) * 1024 + (p >> 2); }

// ================= device scratch =================
__device__ float g_xg[(size_t)BB * SS * GG];            // [t][b][p] xg + bias, permuted
__device__ __half g_xA[2][(size_t)BB * SS * DD];        // x hi / lo(unscaled)
__device__ __half g_WiB[2][DD][GG];                     // Wi hi / lo*2048
__device__ __half g_WhB[2][HH][GG];                     // Wh hi / lo*2048
__device__ __half g_hA[2][128][HH];                     // ping-pong h: rows 0-63 hi, 64-127 lo
__device__ float g_cbuf[BB * HH];
__device__ float g_bias[GG];
__device__ u32 g_flags[16];

// ================= init / prep =================
__global__ void init_state(const float* __restrict__ h0, const float* __restrict__ c0,
                           const float* __restrict__ bi, const float* __restrict__ bh) {
    int i = blockIdx.x * blockDim.x + threadIdx.x;
    if (i < 16) g_flags[i] = 0;
    if (i < BB * HH) {
        int j = i % HH;
        g_cbuf[i] = c0[j];
    }
    if (i < GG) {
        int g = gmap(i);
        g_bias[i] = bi[g] + bh[g];
    }
}

__global__ void init_hA(const float* __restrict__ h0) {
    int idx = blockIdx.x * blockDim.x + threadIdx.x;
    if (idx >= BB * HH) return;
    int b = idx >> 10, j = idx & 1023;
    float v = h0[j];
    __half hi = __float2half(v);
    __half lo = __float2half(v - __half2float(hi));
    g_hA[0][b][j] = hi;
    g_hA[0][b + 64][j] = lo;
}

__global__ void prep_whB(const float* __restrict__ Wh) {
    int idx = blockIdx.x * blockDim.x + threadIdx.x;
    if (idx >= GG * HH) return;
    int k = idx >> 12, p = idx & 4095;
    float v = Wh[(size_t)gmap(p) * HH + k];
    __half hi = __float2half(v);
    __half lo = __float2half((v - __half2float(hi)) * LOSC);
    g_WhB[0][k][p] = hi;
    g_WhB[1][k][p] = lo;
}

__global__ void prep_wiB(const float* __restrict__ Wi) {
    int idx = blockIdx.x * blockDim.x + threadIdx.x;
    if (idx >= GG * DD) return;
    int k = idx >> 12, p = idx & 4095;
    float v = Wi[(size_t)gmap(p) * DD + k];
    __half hi = __float2half(v);
    __half lo = __float2half((v - __half2float(hi)) * LOSC);
    g_WiB[0][k][p] = hi;
    g_WiB[1][k][p] = lo;
}

__global__ void prep_xA(const float* __restrict__ x) {
    size_t i4 = (size_t)blockIdx.x * blockDim.x + threadIdx.x;
    if (i4 >= (size_t)BB * SS * DD / 4) return;
    float4 v = *(const float4*)(x + i4 * 4);
    __half h0 = __float2half(v.x), h1 = __float2half(v.y);
    __half h2 = __float2half(v.z), h3 = __float2half(v.w);
    __half l0 = __float2half(v.x - __half2float(h0));
    __half l1 = __float2half(v.y - __half2float(h1));
    __half l2 = __float2half(v.z - __half2float(h2));
    __half l3 = __float2half(v.w - __half2float(h3));
    __half2 hp0 = {h0, h1}, hp1 = {h2, h3}, lp0 = {l0, l1}, lp1 = {l2, l3};
    uint2 hw = {*(u32*)&hp0, *(u32*)&hp1};
    uint2 lw = {*(u32*)&lp0, *(u32*)&lp1};
    *(uint2*)(&g_xA[0][0] + i4 * 4) = hw;
    *(uint2*)(&g_xA[1][0] + i4 * 4) = lw;
}

// ================= input GEMM: fp16 split-2, 3 products, N=128 tiles ========
// CTA: 128 real M rows (2 subtiles x [64 hi; 64 lo] stacked), N=128, K chunks 64.
// Warp tiling 4M x 2N (warp = 32 real rows x 64 cols): LDS = A*2 + B*4 = 192KB/chunk.

#define GA_STRIDE 36864
#define GB_BASE   110592
#define GB_STRIDE 34816
#define GEMM_SMEM 215040

extern __shared__ char smx[];

__device__ __forceinline__ void g_loadA(u32 dst, int m0, int k0, int tid) {
#pragma unroll
    for (int i = 0; i < 8; i++) {
        int o = tid + i * 256;                 // 0..2047
        int row = o >> 3, seg = o & 7;
        int st = row >> 7, r = row & 127;
        int sp = r >> 6;
        int srow = m0 + st * 64 + (r & 63);
        cp_async16(dst + st * 18432 + r * 144 + seg * 16,
                   (const char*)(&g_xA[sp][0] + (size_t)srow * DD + k0) + seg * 16);
    }
}
__device__ __forceinline__ void g_loadB(u32 dst, int n0, int k0, int tid) {
#pragma unroll
    for (int i = 0; i < 8; i++) {
        int o = tid + i * 256;                 // 0..2047
        int sp = o >> 10, r = (o & 1023) >> 4, seg = o & 15;
        cp_async16(dst + sp * 17408 + r * 272 + seg * 16,
                   (const char*)(&g_WiB[sp][k0 + r][n0]) + seg * 16);
    }
}

__global__ __launch_bounds__(256, 1) void gemm_xg_mma() {
    const int tid = threadIdx.x;
    const int wid = tid >> 5, lane = tid & 31;
    const int wm = wid & 3, wn = wid >> 2;
    const int n0 = blockIdx.x * 128;
    const int m0 = blockIdx.y * 128;
    const u32 sb = smem_u32(smx);

    float accH0[2][8][4], accH1[2][8][4], accL[2][8][4];
#pragma unroll
    for (int mt = 0; mt < 2; mt++)
#pragma unroll
        for (int b = 0; b < 8; b++)
#pragma unroll
            for (int c = 0; c < 4; c++) {
                accH0[mt][b][c] = 0.f; accH1[mt][b][c] = 0.f; accL[mt][b][c] = 0.f;
            }

    // preload chunks 0, 1
    g_loadA(sb + 0 * GA_STRIDE, m0, 0, tid);
    g_loadB(sb + GB_BASE + 0 * GB_STRIDE, n0, 0, tid);
    cp_commit();
    g_loadA(sb + 1 * GA_STRIDE, m0, 64, tid);
    g_loadB(sb + GB_BASE + 1 * GB_STRIDE, n0, 64, tid);
    cp_commit();

    // warp wm: subtile st = wm>>1, local rows (wm&1)*32 .. +32 (hi), +64 rows (lo)
    const u32 a_ro = (wm >> 1) * 18432 + ((wm & 1) * 32 + (lane & 15)) * 144 + (lane >> 4) * 16;
    const u32 b_ro = (lane & 15) * 272 + (lane >> 4) * 16 + wn * 128;

    for (int cc = 0; cc < 16; cc++) {
        if (cc < 15) cp_wait<1>(); else cp_wait<0>();
        __syncthreads();
        if (cc < 14) {
            int nx = (cc + 2) % 3;
            g_loadA(sb + nx * GA_STRIDE, m0, (cc + 2) * 64, tid);
            g_loadB(sb + GB_BASE + nx * GB_STRIDE, n0, (cc + 2) * 64, tid);
            cp_commit();
        }

        const u32 Ab = sb + (cc % 3) * GA_STRIDE;
        const u32 Bb = sb + GB_BASE + (cc % 3) * GB_STRIDE;
#pragma unroll
        for (int kk = 0; kk < 4; kk++) {
            u32 aaddr = Ab + a_ro + kk * 32;
            u32 ah0[4], ah1[4], al0[4], al1[4];
            ldsm_x4(aaddr, ah0[0], ah0[1], ah0[2], ah0[3]);                 // hi rows 0-15
            ldsm_x4(aaddr + 16 * 144, ah1[0], ah1[1], ah1[2], ah1[3]);      // hi rows 16-31
            ldsm_x4(aaddr + 64 * 144, al0[0], al0[1], al0[2], al0[3]);      // lo rows 0-15
            ldsm_x4(aaddr + 80 * 144, al1[0], al1[1], al1[2], al1[3]);      // lo rows 16-31
            u32 bk = Bb + b_ro + kk * 16 * 272;
#pragma unroll
            for (int n16 = 0; n16 < 4; n16++) {
                u32 b0, b1, b2, b3, c0, c1, c2, c3;
                ldsm_x4t(bk + n16 * 32, b0, b1, b2, b3);                    // B_hi
                ldsm_x4t(bk + 17408 + n16 * 32, c0, c1, c2, c3);            // B_lo (scaled)
                mma16816(accH0[0][n16 * 2], ah0[0], ah0[1], ah0[2], ah0[3], b0, b1);
                mma16816(accH0[0][n16 * 2 + 1], ah0[0], ah0[1], ah0[2], ah0[3], b2, b3);
                mma16816(accH0[1][n16 * 2], ah1[0], ah1[1], ah1[2], ah1[3], b0, b1);
                mma16816(accH0[1][n16 * 2 + 1], ah1[0], ah1[1], ah1[2], ah1[3], b2, b3);
                mma16816(accH1[0][n16 * 2], al0[0], al0[1], al0[2], al0[3], b0, b1);
                mma16816(accH1[0][n16 * 2 + 1], al0[0], al0[1], al0[2], al0[3], b2, b3);
                mma16816(accH1[1][n16 * 2], al1[0], al1[1], al1[2], al1[3], b0, b1);
                mma16816(accH1[1][n16 * 2 + 1], al1[0], al1[1], al1[2], al1[3], b2, b3);
                mma16816(accL[0][n16 * 2], ah0[0], ah0[1], ah0[2], ah0[3], c0, c1);
                mma16816(accL[0][n16 * 2 + 1], ah0[0], ah0[1], ah0[2], ah0[3], c2, c3);
                mma16816(accL[1][n16 * 2], ah1[0], ah1[1], ah1[2], ah1[3], c0, c1);
                mma16816(accL[1][n16 * 2 + 1], ah1[0], ah1[1], ah1[2], ah1[3], c2, c3);
            }
        }
    }

    // epilogue: all-in-register combine (hi/lo products share real rows)
    const int g = lane >> 2, tq = lane & 3;
#pragma unroll
    for (int mt = 0; mt < 2; mt++) {
        const int rbase = m0 + (wm >> 1) * 64 + (wm & 1) * 32 + mt * 16 + g;
#pragma unroll
        for (int nt = 0; nt < 8; nt++) {
            int c = wn * 64 + nt * 8 + tq * 2;
            float bz0 = g_bias[n0 + c], bz1 = g_bias[n0 + c + 1];
            {
                int mg = rbase;
                float v0 = accH0[mt][nt][0] + accH1[mt][nt][0] + ILOSC * accL[mt][nt][0] + bz0;
                float v1 = accH0[mt][nt][1] + accH1[mt][nt][1] + ILOSC * accL[mt][nt][1] + bz1;
                int bb = mg >> 9, tt = mg & 511;
                *(float2*)&g_xg[((size_t)tt * BB + bb) * GG + n0 + c] = make_float2(v0, v1);
            }
            {
                int mg = rbase + 8;
                float v0 = accH0[mt][nt][2] + accH1[mt][nt][2] + ILOSC * accL[mt][nt][2] + bz0;
                float v1 = accH0[mt][nt][3] + accH1[mt][nt][3] + ILOSC * accL[mt][nt][3] + bz1;
                int bb = mg >> 9, tt = mg & 511;
                *(float2*)&g_xg[((size_t)tt * BB + bb) * GG + n0 + c] = make_float2(v0, v1);
            }
        }
    }
}

// ================= persistent recurrent kernel =================
// 128 CTAs, 256 threads. CTA s: 32 permuted cols (8 units). Wh resident in SMEM.
// Depth-3 A buffers, one barrier per chunk. Per-warp flag release (64 arrivals
// per flag group per step): h-stores -> syncwarp -> lane0 red.release.

#define PB 0
#define PA_BASE 163840
#define PA_STRIDE 18432
#define PXG 219136
#define PERSIST_SMEM 227328

__device__ __forceinline__ void p_loadA(u32 dst, const __half* hA, int k0, int tid) {
#pragma unroll
    for (int i = 0; i < 4; i++) {
        int o = tid + i * 256;
        int row = o >> 3, seg = o & 7;
        cp_async16_cg(dst + row * 144 + seg * 16,
                      (const char*)(hA + (size_t)row * HH + k0) + seg * 16);
    }
}

__device__ __forceinline__ void wait_step(u32 target, int tid) {
    bool ok = true;
    if (tid < 16) ok = (ld_acq(&g_flags[tid]) >= target);
    while (!__syncthreads_and(ok)) {
        if (tid < 16) ok = (ld_acq(&g_flags[tid]) >= target);
    }
}

__global__ __launch_bounds__(256, 1) void lstm_persist(float* __restrict__ out) {
    const int tid = threadIdx.x;
    const int wid = tid >> 5, lane = tid & 31;
    const int wm = wid & 3, wn = wid >> 2;
    const int s = blockIdx.x;
    const int c0 = s * 32;
    const int j0 = s * 8;
    const u32 sb = smem_u32(smx);
    float* xs = (float*)(smx + PXG);

    // ---- resident Wh tiles (hi at +0, lo-scaled at +81920), 80B rows ----
#pragma unroll
    for (int i = 0; i < 32; i++) {
        int o = tid + i * 256;
        int sp = o >> 12;
        int rem = o & 4095;
        int k = rem >> 2, seg = rem & 3;
        cp_async16(sb + PB + sp * 81920 + k * 80 + seg * 16,
                   (const char*)(&g_WhB[sp][k][c0]) + seg * 16);
    }
    cp_commit();
    cp_wait<0>();
    __syncthreads();

    // lane cell mapping
    const int g = lane >> 2, tq = lane & 3;
    const int brow = wm * 16 + g + ((tq & 1) ? 8 : 0);
    const int u0 = wn * 4 + (tq >> 1);
    float cr[2];
#pragma unroll
    for (int nt = 0; nt < 2; nt++) cr[nt] = g_cbuf[(size_t)brow * HH + j0 + u0 + nt * 2];

    const u32 a_ro = (wm * 16 + (lane & 15)) * 144 + (lane >> 4) * 16;
    const u32 b_cb = (wn * 16 + (lane >> 4) * 8) * 2;
    const u32 bufs[3] = {sb + PA_BASE, sb + PA_BASE + PA_STRIDE, sb + PA_BASE + 2 * PA_STRIDE};

    for (int t = 0; t < SS; t++) {
        const int ping = t & 1;
        const __half* hA = &g_hA[ping][0][0];

        wait_step(64u * (u32)t, tid);

        float p0[2][4], p1[2][4], p2[2][4];
#pragma unroll
        for (int nt = 0; nt < 2; nt++)
#pragma unroll
            for (int qq = 0; qq < 4; qq++) { p0[nt][qq] = 0.f; p1[nt][qq] = 0.f; p2[nt][qq] = 0.f; }

        // xs prefetch + chunk 0 in one commit group; chunk 1 second group
#pragma unroll
        for (int i = 0; i < 2; i++) {
            int o = tid + i * 256;
            int b = o >> 3, seg = o & 7;
            cp_async16(sb + PXG + b * 128 + seg * 16,
                       (const char*)(g_xg + ((size_t)t * BB + b) * GG + c0) + seg * 16);
        }
        p_loadA(bufs[0], hA, 0, tid);
        cp_commit();
        p_loadA(bufs[1], hA, 64, tid);
        cp_commit();

        for (int cc = 0; cc < 16; cc++) {
            if (cc < 15) cp_wait<1>(); else cp_wait<0>();
            __syncthreads();
            if (cc < 14) {
                p_loadA(bufs[(cc + 2) % 3], hA, (cc + 2) * 64, tid);
                cp_commit();
            }

            const u32 Ab = bufs[cc % 3];
#pragma unroll
            for (int kk = 0; kk < 4; kk++) {
                u32 a0, a1, a2, a3, a4, a5, a6, a7;
                u32 aaddr = Ab + a_ro + kk * 32;
                ldsm_x4(aaddr, a0, a1, a2, a3);                // h_hi rows
                ldsm_x4(aaddr + 64 * 144, a4, a5, a6, a7);     // h_lo rows
                u32 b0, b1, b2, b3, b4, b5, b6, b7;
                u32 baddr = sb + PB + (cc * 64 + kk * 16 + (lane & 15)) * 80 + b_cb;
                ldsm_x4t(baddr, b0, b1, b2, b3);               // W_hi
                ldsm_x4t(baddr + 81920, b4, b5, b6, b7);       // W_lo*2048
                mma16816(p0[0], a0, a1, a2, a3, b0, b1);
                mma16816(p0[1], a0, a1, a2, a3, b2, b3);
                mma16816(p1[0], a4, a5, a6, a7, b0, b1);
                mma16816(p1[1], a4, a5, a6, a7, b2, b3);
                mma16816(p2[0], a0, a1, a2, a3, b4, b5);
                mma16816(p2[1], a0, a1, a2, a3, b6, b7);
            }
        }

        // in-register gate combine + xs
        float hv[2];
        u32 hiw[2], low[2];
#pragma unroll
        for (int nt = 0; nt < 2; nt++) {
            float q0 = p0[nt][0] + p1[nt][0] + ILOSC * p2[nt][0];
            float q1 = p0[nt][1] + p1[nt][1] + ILOSC * p2[nt][1];
            float q2 = p0[nt][2] + p1[nt][2] + ILOSC * p2[nt][2];
            float q3 = p0[nt][3] + p1[nt][3] + ILOSC * p2[nt][3];
            int b0r = wm * 16 + g;
            int col = wn * 16 + nt * 8 + tq * 2;
            q0 += xs[b0r * 32 + col];       q1 += xs[b0r * 32 + col + 1];
            q2 += xs[(b0r + 8) * 32 + col]; q3 += xs[(b0r + 8) * 32 + col + 1];
            float r0 = __shfl_xor_sync(0xFFFFFFFFu, q0, 1);
            float r1 = __shfl_xor_sync(0xFFFFFFFFu, q1, 1);
            float r2 = __shfl_xor_sync(0xFFFFFFFFu, q2, 1);
            float r3 = __shfl_xor_sync(0xFFFFFFFFu, q3, 1);
            float gi, gf, gg, go;
            if ((tq & 1) == 0) { gi = q0; gf = q1; gg = r0; go = r1; }
            else               { gi = r2; gf = r3; gg = q2; go = q3; }
            float c = sigf(gf) * cr[nt] + sigf(gi) * tanhf(gg);
            cr[nt] = c;
            float h = sigf(go) * tanhf(c);
            hv[nt] = h;
            __half hi = __float2half(h);
            __half lo = __float2half(h - __half2float(hi));
            hiw[nt] = *(unsigned short*)&hi;
            low[nt] = *(unsigned short*)&lo;
        }
        // next-step h tiles, then per-warp release (critical path),
        // then out stores (off the critical path)
#pragma unroll
        for (int nt = 0; nt < 2; nt++) {
            int j = j0 + u0 + nt * 2;
            *(unsigned short*)&g_hA[ping ^ 1][brow][j] = (unsigned short)hiw[nt];
            *(unsigned short*)&g_hA[ping ^ 1][brow + 64][j] = (unsigned short)low[nt];
        }
        __syncwarp();
        if (lane == 0) red_release(&g_flags[s >> 3]);
#pragma unroll
        for (int nt = 0; nt < 2; nt++)
            out[((size_t)brow * SS + t) * HH + j0 + u0 + nt * 2] = hv[nt];
    }

#pragma unroll
    for (int nt = 0; nt < 2; nt++)
        g_cbuf[(size_t)brow * HH + j0 + u0 + nt * 2] = cr[nt];
}

// ================= tail =================
__global__ void write_tail(float* __restrict__ out, long long hsz, int want_c) {
    int i = blockIdx.x * blockDim.x + threadIdx.x;
    if (i < BB * HH) {
        int b = i / HH, j = i % HH;
        out[hsz + i] = out[((size_t)b * SS + (SS - 1)) * HH + j];
        if (want_c) out[hsz + (long long)BB * HH + i] = g_cbuf[i];
    }
}

// ================= launch =================
extern "C" void kernel_launch(void* const* d_in, const int* in_sizes, int n_in,
                              void* d_out, int out_size) {
    const float* x  = (const float*)d_in[0];
    const float* h0 = (const float*)d_in[1];
    const float* c0 = (const float*)d_in[2];
    const float* Wi = (const float*)d_in[3];
    const float* bi = (const float*)d_in[4];
    const float* Wh = (const float*)d_in[5];
    const float* bh = (const float*)d_in[6];
    float* out = (float*)d_out;

    cudaFuncSetAttribute(gemm_xg_mma, cudaFuncAttributeMaxDynamicSharedMemorySize, GEMM_SMEM);
    cudaFuncSetAttribute(lstm_persist, cudaFuncAttributeMaxDynamicSharedMemorySize, PERSIST_SMEM);

    init_state<<<(BB * HH + 255) / 256, 256>>>(h0, c0, bi, bh);
    init_hA<<<(BB * HH + 255) / 256, 256>>>(h0);
    prep_whB<<<(GG * HH) / 256, 256>>>(Wh);
    prep_wiB<<<(GG * DD) / 256, 256>>>(Wi);
    prep_xA<<<(int)(((size_t)BB * SS * DD / 4) / 256), 256>>>(x);

    dim3 gg(GG / 128, (BB * SS) / 128);
    gemm_xg_mma<<<gg, 256, GEMM_SMEM>>>();

    lstm_persist<<<128, 256, PERSIST_SMEM>>>(out);

    long long hsz = (long long)BB * SS * HH;
    int want_h = ((long long)out_size >= hsz + (long long)BB * HH) ? 1 : 0;
    int want_c = ((long long)out_size >= hsz + 2LL * BB * HH) ? 1 : 0;
    if (want_h) {
        write_tail<<<(BB * HH + 255) / 256, 256>>>(out, hsz, want_c);
    }
}

// round 14
// speedup vs baseline: 1.0309x; 1.0309x over previous
#include <cuda_runtime.h>
#include <cuda_fp16.h>
#include <math.h>

#define BB 64
#define SS 512
#define DD 1024
#define HH 1024
#define GG 4096
#define LOSC 2048.0f
#define ILOSC 0.00048828125f

typedef unsigned int u32;

// ================= helpers =================
__device__ __forceinline__ void cp_async16(unsigned s, const void* g) {
    asm volatile("cp.async.ca.shared.global [%0], [%1], 16;" :: "r"(s), "l"(g));
}
__device__ __forceinline__ void cp_async16_cg(unsigned s, const void* g) {
    asm volatile("cp.async.cg.shared.global [%0], [%1], 16;" :: "r"(s), "l"(g));
}
__device__ __forceinline__ void cp_commit() { asm volatile("cp.async.commit_group;"); }
template<int N> __device__ __forceinline__ void cp_wait() {
    asm volatile("cp.async.wait_group %0;" :: "n"(N));
}
__device__ __forceinline__ u32 smem_u32(const void* p) {
    u32 a;
    asm("{ .reg .u64 t; cvta.to.shared.u64 t, %1; cvt.u32.u64 %0, t; }" : "=r"(a) : "l"(p));
    return a;
}
__device__ __forceinline__ void ldsm_x4(u32 addr, u32& r0, u32& r1, u32& r2, u32& r3) {
    asm volatile("ldmatrix.sync.aligned.m8n8.x4.shared.b16 {%0,%1,%2,%3}, [%4];"
                 : "=r"(r0), "=r"(r1), "=r"(r2), "=r"(r3) : "r"(addr));
}
__device__ __forceinline__ void ldsm_x4t(u32 addr, u32& r0, u32& r1, u32& r2, u32& r3) {
    asm volatile("ldmatrix.sync.aligned.m8n8.x4.trans.shared.b16 {%0,%1,%2,%3}, [%4];"
                 : "=r"(r0), "=r"(r1), "=r"(r2), "=r"(r3) : "r"(addr));
}
__device__ __forceinline__ void mma16816(float* c, u32 a0, u32 a1, u32 a2, u32 a3, u32 b0, u32 b1) {
    asm volatile("mma.sync.aligned.m16n8k16.row.col.f32.f16.f16.f32 "
                 "{%0,%1,%2,%3},{%4,%5,%6,%7},{%8,%9},{%0,%1,%2,%3};"
                 : "+f"(c[0]), "+f"(c[1]), "+f"(c[2]), "+f"(c[3])
                 : "r"(a0), "r"(a1), "r"(a2), "r"(a3), "r"(b0), "r"(b1));
}
__device__ __forceinline__ u32 ld_acq(const u32* p) {
    u32 v;
    asm volatile("ld.acquire.gpu.global.u32 %0, [%1];" : "=r"(v) : "l"(p) : "memory");
    return v;
}
__device__ __forceinline__ void red_release(u32* p) {
    asm volatile("red.release.gpu.global.add.u32 [%0], 1;" :: "l"(p) : "memory");
}
__device__ __forceinline__ float sigf(float x) {
    return __fmaf_rn(0.5f, tanhf(0.5f * x), 0.5f);
}

__host__ __device__ __forceinline__ int gmap(int p) { return (p & 3) * 1024 + (p >> 2); }

// ================= device scratch =================
__device__ float g_xg[(size_t)BB * SS * GG];            // [t][b][p] xg + bias, permuted
__device__ __half g_xA[2][(size_t)BB * SS * DD];        // x hi / lo(unscaled)
__device__ __half g_WiB[2][DD][GG];                     // Wi hi / lo*2048
__device__ __half g_WhB[2][HH][GG];                     // Wh hi / lo*2048
__device__ __half g_hA[2][128][HH];                     // ping-pong h: rows 0-63 hi, 64-127 lo
__device__ float g_cbuf[BB * HH];
__device__ float g_bias[GG];
__device__ u32 g_flags[16];

// ================= init / prep =================
__global__ void init_state(const float* __restrict__ h0, const float* __restrict__ c0,
                           const float* __restrict__ bi, const float* __restrict__ bh) {
    int i = blockIdx.x * blockDim.x + threadIdx.x;
    if (i < 16) g_flags[i] = 0;
    if (i < BB * HH) {
        int j = i % HH;
        g_cbuf[i] = c0[j];
    }
    if (i < GG) {
        int g = gmap(i);
        g_bias[i] = bi[g] + bh[g];
    }
}

__global__ void init_hA(const float* __restrict__ h0) {
    int idx = blockIdx.x * blockDim.x + threadIdx.x;
    if (idx >= BB * HH) return;
    int b = idx >> 10, j = idx & 1023;
    float v = h0[j];
    __half hi = __float2half(v);
    __half lo = __float2half(v - __half2float(hi));
    g_hA[0][b][j] = hi;
    g_hA[0][b + 64][j] = lo;
}

__global__ void prep_whB(const float* __restrict__ Wh) {
    int idx = blockIdx.x * blockDim.x + threadIdx.x;
    if (idx >= GG * HH) return;
    int k = idx >> 12, p = idx & 4095;
    float v = Wh[(size_t)gmap(p) * HH + k];
    __half hi = __float2half(v);
    __half lo = __float2half((v - __half2float(hi)) * LOSC);
    g_WhB[0][k][p] = hi;
    g_WhB[1][k][p] = lo;
}

__global__ void prep_wiB(const float* __restrict__ Wi) {
    int idx = blockIdx.x * blockDim.x + threadIdx.x;
    if (idx >= GG * DD) return;
    int k = idx >> 12, p = idx & 4095;
    float v = Wi[(size_t)gmap(p) * DD + k];
    __half hi = __float2half(v);
    __half lo = __float2half((v - __half2float(hi)) * LOSC);
    g_WiB[0][k][p] = hi;
    g_WiB[1][k][p] = lo;
}

__global__ void prep_xA(const float* __restrict__ x) {
    size_t i4 = (size_t)blockIdx.x * blockDim.x + threadIdx.x;
    if (i4 >= (size_t)BB * SS * DD / 4) return;
    float4 v = *(const float4*)(x + i4 * 4);
    __half h0 = __float2half(v.x), h1 = __float2half(v.y);
    __half h2 = __float2half(v.z), h3 = __float2half(v.w);
    __half l0 = __float2half(v.x - __half2float(h0));
    __half l1 = __float2half(v.y - __half2float(h1));
    __half l2 = __float2half(v.z - __half2float(h2));
    __half l3 = __float2half(v.w - __half2float(h3));
    __half2 hp0 = {h0, h1}, hp1 = {h2, h3}, lp0 = {l0, l1}, lp1 = {l2, l3};
    uint2 hw = {*(u32*)&hp0, *(u32*)&hp1};
    uint2 lw = {*(u32*)&lp0, *(u32*)&lp1};
    *(uint2*)(&g_xA[0][0] + i4 * 4) = hw;
    *(uint2*)(&g_xA[1][0] + i4 * 4) = lw;
}

// ================= input GEMM: fp16 split-2, 3 products, N=128 tiles ========
// CTA: 128 real M rows (2 subtiles x [64 hi; 64 lo] stacked), N=128, K chunks 64.
// Warp tiling 4M x 2N (warp = 32 real rows x 64 cols): LDS = A*2 + B*4 = 192KB/chunk.

#define GA_STRIDE 36864
#define GB_BASE   110592
#define GB_STRIDE 34816
#define GEMM_SMEM 215040

extern __shared__ char smx[];

__device__ __forceinline__ void g_loadA(u32 dst, int m0, int k0, int tid) {
#pragma unroll
    for (int i = 0; i < 8; i++) {
        int o = tid + i * 256;                 // 0..2047
        int row = o >> 3, seg = o & 7;
        int st = row >> 7, r = row & 127;
        int sp = r >> 6;
        int srow = m0 + st * 64 + (r & 63);
        cp_async16(dst + st * 18432 + r * 144 + seg * 16,
                   (const char*)(&g_xA[sp][0] + (size_t)srow * DD + k0) + seg * 16);
    }
}
__device__ __forceinline__ void g_loadB(u32 dst, int n0, int k0, int tid) {
#pragma unroll
    for (int i = 0; i < 8; i++) {
        int o = tid + i * 256;                 // 0..2047
        int sp = o >> 10, r = (o & 1023) >> 4, seg = o & 15;
        cp_async16(dst + sp * 17408 + r * 272 + seg * 16,
                   (const char*)(&g_WiB[sp][k0 + r][n0]) + seg * 16);
    }
}

__global__ __launch_bounds__(256, 1) void gemm_xg_mma() {
    const int tid = threadIdx.x;
    const int wid = tid >> 5, lane = tid & 31;
    const int wm = wid & 3, wn = wid >> 2;
    const int n0 = blockIdx.x * 128;
    const int m0 = blockIdx.y * 128;
    const u32 sb = smem_u32(smx);

    float accH0[2][8][4], accH1[2][8][4], accL[2][8][4];
#pragma unroll
    for (int mt = 0; mt < 2; mt++)
#pragma unroll
        for (int b = 0; b < 8; b++)
#pragma unroll
            for (int c = 0; c < 4; c++) {
                accH0[mt][b][c] = 0.f; accH1[mt][b][c] = 0.f; accL[mt][b][c] = 0.f;
            }

    // preload chunks 0, 1
    g_loadA(sb + 0 * GA_STRIDE, m0, 0, tid);
    g_loadB(sb + GB_BASE + 0 * GB_STRIDE, n0, 0, tid);
    cp_commit();
    g_loadA(sb + 1 * GA_STRIDE, m0, 64, tid);
    g_loadB(sb + GB_BASE + 1 * GB_STRIDE, n0, 64, tid);
    cp_commit();

    // warp wm: subtile st = wm>>1, local rows (wm&1)*32 .. +32 (hi), +64 rows (lo)
    const u32 a_ro = (wm >> 1) * 18432 + ((wm & 1) * 32 + (lane & 15)) * 144 + (lane >> 4) * 16;
    const u32 b_ro = (lane & 15) * 272 + (lane >> 4) * 16 + wn * 128;

    for (int cc = 0; cc < 16; cc++) {
        if (cc < 15) cp_wait<1>(); else cp_wait<0>();
        __syncthreads();
        if (cc < 14) {
            int nx = (cc + 2) % 3;
            g_loadA(sb + nx * GA_STRIDE, m0, (cc + 2) * 64, tid);
            g_loadB(sb + GB_BASE + nx * GB_STRIDE, n0, (cc + 2) * 64, tid);
            cp_commit();
        }

        const u32 Ab = sb + (cc % 3) * GA_STRIDE;
        const u32 Bb = sb + GB_BASE + (cc % 3) * GB_STRIDE;
#pragma unroll
        for (int kk = 0; kk < 4; kk++) {
            u32 aaddr = Ab + a_ro + kk * 32;
            u32 ah0[4], ah1[4], al0[4], al1[4];
            ldsm_x4(aaddr, ah0[0], ah0[1], ah0[2], ah0[3]);                 // hi rows 0-15
            ldsm_x4(aaddr + 16 * 144, ah1[0], ah1[1], ah1[2], ah1[3]);      // hi rows 16-31
            ldsm_x4(aaddr + 64 * 144, al0[0], al0[1], al0[2], al0[3]);      // lo rows 0-15
            ldsm_x4(aaddr + 80 * 144, al1[0], al1[1], al1[2], al1[3]);      // lo rows 16-31
            u32 bk = Bb + b_ro + kk * 16 * 272;
#pragma unroll
            for (int n16 = 0; n16 < 4; n16++) {
                u32 b0, b1, b2, b3, c0, c1, c2, c3;
                ldsm_x4t(bk + n16 * 32, b0, b1, b2, b3);                    // B_hi
                ldsm_x4t(bk + 17408 + n16 * 32, c0, c1, c2, c3);            // B_lo (scaled)
                mma16816(accH0[0][n16 * 2], ah0[0], ah0[1], ah0[2], ah0[3], b0, b1);
                mma16816(accH0[0][n16 * 2 + 1], ah0[0], ah0[1], ah0[2], ah0[3], b2, b3);
                mma16816(accH0[1][n16 * 2], ah1[0], ah1[1], ah1[2], ah1[3], b0, b1);
                mma16816(accH0[1][n16 * 2 + 1], ah1[0], ah1[1], ah1[2], ah1[3], b2, b3);
                mma16816(accH1[0][n16 * 2], al0[0], al0[1], al0[2], al0[3], b0, b1);
                mma16816(accH1[0][n16 * 2 + 1], al0[0], al0[1], al0[2], al0[3], b2, b3);
                mma16816(accH1[1][n16 * 2], al1[0], al1[1], al1[2], al1[3], b0, b1);
                mma16816(accH1[1][n16 * 2 + 1], al1[0], al1[1], al1[2], al1[3], b2, b3);
                mma16816(accL[0][n16 * 2], ah0[0], ah0[1], ah0[2], ah0[3], c0, c1);
                mma16816(accL[0][n16 * 2 + 1], ah0[0], ah0[1], ah0[2], ah0[3], c2, c3);
                mma16816(accL[1][n16 * 2], ah1[0], ah1[1], ah1[2], ah1[3], c0, c1);
                mma16816(accL[1][n16 * 2 + 1], ah1[0], ah1[1], ah1[2], ah1[3], c2, c3);
            }
        }
    }

    // epilogue: all-in-register combine (hi/lo products share real rows)
    const int g = lane >> 2, tq = lane & 3;
#pragma unroll
    for (int mt = 0; mt < 2; mt++) {
        const int rbase = m0 + (wm >> 1) * 64 + (wm & 1) * 32 + mt * 16 + g;
#pragma unroll
        for (int nt = 0; nt < 8; nt++) {
            int c = wn * 64 + nt * 8 + tq * 2;
            float bz0 = g_bias[n0 + c], bz1 = g_bias[n0 + c + 1];
            {
                int mg = rbase;
                float v0 = accH0[mt][nt][0] + accH1[mt][nt][0] + ILOSC * accL[mt][nt][0] + bz0;
                float v1 = accH0[mt][nt][1] + accH1[mt][nt][1] + ILOSC * accL[mt][nt][1] + bz1;
                int bb = mg >> 9, tt = mg & 511;
                *(float2*)&g_xg[((size_t)tt * BB + bb) * GG + n0 + c] = make_float2(v0, v1);
            }
            {
                int mg = rbase + 8;
                float v0 = accH0[mt][nt][2] + accH1[mt][nt][2] + ILOSC * accL[mt][nt][2] + bz0;
                float v1 = accH0[mt][nt][3] + accH1[mt][nt][3] + ILOSC * accL[mt][nt][3] + bz1;
                int bb = mg >> 9, tt = mg & 511;
                *(float2*)&g_xg[((size_t)tt * BB + bb) * GG + n0 + c] = make_float2(v0, v1);
            }
        }
    }
}

// ================= persistent recurrent kernel (R12 protocol, verbatim) =====
// 128 CTAs, 256 threads. CTA s: 32 permuted cols (8 units). Wh resident in SMEM.
// Depth-3 A buffers, one barrier per chunk, nanosleep-backed poll, tid0 release.

#define PB 0
#define PA_BASE 163840
#define PA_STRIDE 18432
#define PXG 219136
#define PERSIST_SMEM 227328

__device__ __forceinline__ void p_loadA(u32 dst, const __half* hA, int k0, int tid) {
#pragma unroll
    for (int i = 0; i < 4; i++) {
        int o = tid + i * 256;
        int row = o >> 3, seg = o & 7;
        cp_async16_cg(dst + row * 144 + seg * 16,
                      (const char*)(hA + (size_t)row * HH + k0) + seg * 16);
    }
}

__device__ __forceinline__ void wait_step(u32 target, int tid) {
    bool ok = true;
    if (tid < 16) ok = (ld_acq(&g_flags[tid]) >= target);
    while (!__syncthreads_and(ok)) {
        __nanosleep(40);
        if (tid < 16) ok = (ld_acq(&g_flags[tid]) >= target);
    }
}

__global__ __launch_bounds__(256, 1) void lstm_persist(float* __restrict__ out) {
    const int tid = threadIdx.x;
    const int wid = tid >> 5, lane = tid & 31;
    const int wm = wid & 3, wn = wid >> 2;
    const int s = blockIdx.x;
    const int c0 = s * 32;
    const int j0 = s * 8;
    const u32 sb = smem_u32(smx);
    float* xs = (float*)(smx + PXG);

    // ---- resident Wh tiles (hi at +0, lo-scaled at +81920), 80B rows ----
#pragma unroll
    for (int i = 0; i < 32; i++) {
        int o = tid + i * 256;
        int sp = o >> 12;
        int rem = o & 4095;
        int k = rem >> 2, seg = rem & 3;
        cp_async16(sb + PB + sp * 81920 + k * 80 + seg * 16,
                   (const char*)(&g_WhB[sp][k][c0]) + seg * 16);
    }
    cp_commit();
    cp_wait<0>();
    __syncthreads();

    // lane cell mapping
    const int g = lane >> 2, tq = lane & 3;
    const int brow = wm * 16 + g + ((tq & 1) ? 8 : 0);
    const int u0 = wn * 4 + (tq >> 1);
    float cr[2];
#pragma unroll
    for (int nt = 0; nt < 2; nt++) cr[nt] = g_cbuf[(size_t)brow * HH + j0 + u0 + nt * 2];

    const u32 a_ro = (wm * 16 + (lane & 15)) * 144 + (lane >> 4) * 16;
    const u32 b_cb = (wn * 16 + (lane >> 4) * 8) * 2;
    const u32 bufs[3] = {sb + PA_BASE, sb + PA_BASE + PA_STRIDE, sb + PA_BASE + 2 * PA_STRIDE};

    for (int t = 0; t < SS; t++) {
        const int ping = t & 1;
        const __half* hA = &g_hA[ping][0][0];

        wait_step(8u * (u32)t, tid);

        float p0[2][4], p1[2][4], p2[2][4];
#pragma unroll
        for (int nt = 0; nt < 2; nt++)
#pragma unroll
            for (int qq = 0; qq < 4; qq++) { p0[nt][qq] = 0.f; p1[nt][qq] = 0.f; p2[nt][qq] = 0.f; }

        // xs prefetch + chunk 0 in one commit group; chunk 1 second group
#pragma unroll
        for (int i = 0; i < 2; i++) {
            int o = tid + i * 256;
            int b = o >> 3, seg = o & 7;
            cp_async16(sb + PXG + b * 128 + seg * 16,
                       (const char*)(g_xg + ((size_t)t * BB + b) * GG + c0) + seg * 16);
        }
        p_loadA(bufs[0], hA, 0, tid);
        cp_commit();
        p_loadA(bufs[1], hA, 64, tid);
        cp_commit();

        for (int cc = 0; cc < 16; cc++) {
            if (cc < 15) cp_wait<1>(); else cp_wait<0>();
            __syncthreads();
            if (cc < 14) {
                p_loadA(bufs[(cc + 2) % 3], hA, (cc + 2) * 64, tid);
                cp_commit();
            }

            const u32 Ab = bufs[cc % 3];
#pragma unroll
            for (int kk = 0; kk < 4; kk++) {
                u32 a0, a1, a2, a3, a4, a5, a6, a7;
                u32 aaddr = Ab + a_ro + kk * 32;
                ldsm_x4(aaddr, a0, a1, a2, a3);                // h_hi rows
                ldsm_x4(aaddr + 64 * 144, a4, a5, a6, a7);     // h_lo rows
                u32 b0, b1, b2, b3, b4, b5, b6, b7;
                u32 baddr = sb + PB + (cc * 64 + kk * 16 + (lane & 15)) * 80 + b_cb;
                ldsm_x4t(baddr, b0, b1, b2, b3);               // W_hi
                ldsm_x4t(baddr + 81920, b4, b5, b6, b7);       // W_lo*2048
                mma16816(p0[0], a0, a1, a2, a3, b0, b1);
                mma16816(p0[1], a0, a1, a2, a3, b2, b3);
                mma16816(p1[0], a4, a5, a6, a7, b0, b1);
                mma16816(p1[1], a4, a5, a6, a7, b2, b3);
                mma16816(p2[0], a0, a1, a2, a3, b4, b5);
                mma16816(p2[1], a0, a1, a2, a3, b6, b7);
            }
        }

        // in-register gate combine + xs
        float hv[2];
        u32 hiw[2], low[2];
#pragma unroll
        for (int nt = 0; nt < 2; nt++) {
            float q0 = p0[nt][0] + p1[nt][0] + ILOSC * p2[nt][0];
            float q1 = p0[nt][1] + p1[nt][1] + ILOSC * p2[nt][1];
            float q2 = p0[nt][2] + p1[nt][2] + ILOSC * p2[nt][2];
            float q3 = p0[nt][3] + p1[nt][3] + ILOSC * p2[nt][3];
            int b0r = wm * 16 + g;
            int col = wn * 16 + nt * 8 + tq * 2;
            q0 += xs[b0r * 32 + col];       q1 += xs[b0r * 32 + col + 1];
            q2 += xs[(b0r + 8) * 32 + col]; q3 += xs[(b0r + 8) * 32 + col + 1];
            float r0 = __shfl_xor_sync(0xFFFFFFFFu, q0, 1);
            float r1 = __shfl_xor_sync(0xFFFFFFFFu, q1, 1);
            float r2 = __shfl_xor_sync(0xFFFFFFFFu, q2, 1);
            float r3 = __shfl_xor_sync(0xFFFFFFFFu, q3, 1);
            float gi, gf, gg, go;
            if ((tq & 1) == 0) { gi = q0; gf = q1; gg = r0; go = r1; }
            else               { gi = r2; gf = r3; gg = q2; go = q3; }
            float c = sigf(gf) * cr[nt] + sigf(gi) * tanhf(gg);
            cr[nt] = c;
            float h = sigf(go) * tanhf(c);
            hv[nt] = h;
            __half hi = __float2half(h);
            __half lo = __float2half(h - __half2float(hi));
            hiw[nt] = *(unsigned short*)&hi;
            low[nt] = *(unsigned short*)&lo;
        }
        // next-step h tiles first (they gate other CTAs)
#pragma unroll
        for (int nt = 0; nt < 2; nt++) {
            int j = j0 + u0 + nt * 2;
            *(unsigned short*)&g_hA[ping ^ 1][brow][j] = (unsigned short)hiw[nt];
            *(unsigned short*)&g_hA[ping ^ 1][brow + 64][j] = (unsigned short)low[nt];
        }
        __syncthreads();
        if (tid == 0) red_release(&g_flags[s >> 3]);
        // out stores off the critical path
#pragma unroll
        for (int nt = 0; nt < 2; nt++)
            out[((size_t)brow * SS + t) * HH + j0 + u0 + nt * 2] = hv[nt];
    }

#pragma unroll
    for (int nt = 0; nt < 2; nt++)
        g_cbuf[(size_t)brow * HH + j0 + u0 + nt * 2] = cr[nt];
}

// ================= tail =================
__global__ void write_tail(float* __restrict__ out, long long hsz, int want_c) {
    int i = blockIdx.x * blockDim.x + threadIdx.x;
    if (i < BB * HH) {
        int b = i / HH, j = i % HH;
        out[hsz + i] = out[((size_t)b * SS + (SS - 1)) * HH + j];
        if (want_c) out[hsz + (long long)BB * HH + i] = g_cbuf[i];
    }
}

// ================= launch =================
extern "C" void kernel_launch(void* const* d_in, const int* in_sizes, int n_in,
                              void* d_out, int out_size) {
    const float* x  = (const float*)d_in[0];
    const float* h0 = (const float*)d_in[1];
    const float* c0 = (const float*)d_in[2];
    const float* Wi = (const float*)d_in[3];
    const float* bi = (const float*)d_in[4];
    const float* Wh = (const float*)d_in[5];
    const float* bh = (const float*)d_in[6];
    float* out = (float*)d_out;

    cudaFuncSetAttribute(gemm_xg_mma, cudaFuncAttributeMaxDynamicSharedMemorySize, GEMM_SMEM);
    cudaFuncSetAttribute(lstm_persist, cudaFuncAttributeMaxDynamicSharedMemorySize, PERSIST_SMEM);

    init_state<<<(BB * HH + 255) / 256, 256>>>(h0, c0, bi, bh);
    init_hA<<<(BB * HH + 255) / 256, 256>>>(h0);
    prep_whB<<<(GG * HH) / 256, 256>>>(Wh);
    prep_wiB<<<(GG * DD) / 256, 256>>>(Wi);
    prep_xA<<<(int)(((size_t)BB * SS * DD / 4) / 256), 256>>>(x);

    dim3 gg(GG / 128, (BB * SS) / 128);
    gemm_xg_mma<<<gg, 256, GEMM_SMEM>>>();

    lstm_persist<<<128, 256, PERSIST_SMEM>>>(out);

    long long hsz = (long long)BB * SS * HH;
    int want_h = ((long long)out_size >= hsz + (long long)BB * HH) ? 1 : 0;
    int want_c = ((long long)out_size >= hsz + 2LL * BB * HH) ? 1 : 0;
    if (want_h) {
        write_tail<<<(BB * HH + 255) / 256, 256>>>(out, hsz, want_c);
    }
}

// round 16
// speedup vs baseline: 1.0658x; 1.0338x over previous
#include <cuda_runtime.h>
#include <cuda_fp16.h>
#include <math.h>

#define BB 64
#define SS 512
#define DD 1024
#define HH 1024
#define GG 4096
#define LOSC 2048.0f
#define ILOSC 0.00048828125f

typedef unsigned int u32;

// ================= helpers =================
__device__ __forceinline__ void cp_async16(unsigned s, const void* g) {
    asm volatile("cp.async.ca.shared.global [%0], [%1], 16;" :: "r"(s), "l"(g));
}
__device__ __forceinline__ void cp_async16_cg(unsigned s, const void* g) {
    asm volatile("cp.async.cg.shared.global [%0], [%1], 16;" :: "r"(s), "l"(g));
}
__device__ __forceinline__ void cp_commit() { asm volatile("cp.async.commit_group;"); }
template<int N> __device__ __forceinline__ void cp_wait() {
    asm volatile("cp.async.wait_group %0;" :: "n"(N));
}
__device__ __forceinline__ u32 smem_u32(const void* p) {
    u32 a;
    asm("{ .reg .u64 t; cvta.to.shared.u64 t, %1; cvt.u32.u64 %0, t; }" : "=r"(a) : "l"(p));
    return a;
}
__device__ __forceinline__ void ldsm_x4(u32 addr, u32& r0, u32& r1, u32& r2, u32& r3) {
    asm volatile("ldmatrix.sync.aligned.m8n8.x4.shared.b16 {%0,%1,%2,%3}, [%4];"
                 : "=r"(r0), "=r"(r1), "=r"(r2), "=r"(r3) : "r"(addr));
}
__device__ __forceinline__ void ldsm_x4t(u32 addr, u32& r0, u32& r1, u32& r2, u32& r3) {
    asm volatile("ldmatrix.sync.aligned.m8n8.x4.trans.shared.b16 {%0,%1,%2,%3}, [%4];"
                 : "=r"(r0), "=r"(r1), "=r"(r2), "=r"(r3) : "r"(addr));
}
__device__ __forceinline__ void mma16816(float* c, u32 a0, u32 a1, u32 a2, u32 a3, u32 b0, u32 b1) {
    asm volatile("mma.sync.aligned.m16n8k16.row.col.f32.f16.f16.f32 "
                 "{%0,%1,%2,%3},{%4,%5,%6,%7},{%8,%9},{%0,%1,%2,%3};"
                 : "+f"(c[0]), "+f"(c[1]), "+f"(c[2]), "+f"(c[3])
                 : "r"(a0), "r"(a1), "r"(a2), "r"(a3), "r"(b0), "r"(b1));
}
__device__ __forceinline__ u32 ld_acq(const u32* p) {
    u32 v;
    asm volatile("ld.acquire.gpu.global.u32 %0, [%1];" : "=r"(v) : "l"(p) : "memory");
    return v;
}
__device__ __forceinline__ void red_release(u32* p) {
    asm volatile("red.release.gpu.global.add.u32 [%0], 1;" :: "l"(p) : "memory");
}
__device__ __forceinline__ float sigf(float x) {
    return __fmaf_rn(0.5f, tanhf(0.5f * x), 0.5f);
}

__host__ __device__ __forceinline__ int gmap(int p) { return (p & 3) * 1024 + (p >> 2); }

// ================= device scratch =================
__device__ float g_xg[(size_t)BB * SS * GG];            // [t][b][p] xg + bias, permuted
__device__ __half g_xA[2][(size_t)BB * SS * DD];        // x hi / lo(unscaled)
__device__ __half g_WiB[2][DD][GG];                     // Wi hi / lo*2048
__device__ __half g_WhB[2][HH][GG];                     // Wh hi / lo*2048
__device__ __half g_hA[2][128][HH];                     // ping-pong h: rows 0-63 hi, 64-127 lo
__device__ float g_cbuf[BB * HH];
__device__ float g_bias[GG];
__device__ u32 g_flags[16];

// ================= init / prep =================
__global__ void init_state(const float* __restrict__ h0, const float* __restrict__ c0,
                           const float* __restrict__ bi, const float* __restrict__ bh) {
    int i = blockIdx.x * blockDim.x + threadIdx.x;
    if (i < 16) g_flags[i] = 0;
    if (i < BB * HH) {
        int j = i % HH;
        g_cbuf[i] = c0[j];
    }
    if (i < GG) {
        int g = gmap(i);
        g_bias[i] = bi[g] + bh[g];
    }
}

__global__ void init_hA(const float* __restrict__ h0) {
    int idx = blockIdx.x * blockDim.x + threadIdx.x;
    if (idx >= BB * HH) return;
    int b = idx >> 10, j = idx & 1023;
    float v = h0[j];
    __half hi = __float2half(v);
    __half lo = __float2half(v - __half2float(hi));
    g_hA[0][b][j] = hi;
    g_hA[0][b + 64][j] = lo;
}

// Coalesced weight prep via smem tile transpose. which=0 -> g_WhB, which=1 -> g_WiB.
// Destination globals referenced from DEVICE code (host &device-symbol is invalid).
__global__ __launch_bounds__(256) void prep_w(const float* __restrict__ W, int which) {
    __shared__ float tile[32][33];
    const int p0 = blockIdx.x * 32;
    const int k0 = blockIdx.y * 32;
    const int tid = threadIdx.x;
    {
        int i = tid >> 3;          // p-local 0..31
        int j = tid & 7;           // k group of 4
        int g = gmap(p0 + i);
        float4 v = *(const float4*)&W[(size_t)g * 1024 + k0 + j * 4];
        tile[i][j * 4 + 0] = v.x;
        tile[i][j * 4 + 1] = v.y;
        tile[i][j * 4 + 2] = v.z;
        tile[i][j * 4 + 3] = v.w;
    }
    __syncthreads();
    {
        int pp = tid & 31;         // p-local
        int kb = tid >> 5;         // 0..7
        __half* dst_hi = which ? &g_WiB[0][0][0] : &g_WhB[0][0][0];
        __half* dst_lo = which ? &g_WiB[1][0][0] : &g_WhB[1][0][0];
#pragma unroll
        for (int it = 0; it < 4; it++) {
            int kk = kb * 4 + it;
            float v = tile[pp][kk];
            __half hi = __float2half(v);
            __half lo = __float2half((v - __half2float(hi)) * LOSC);
            dst_hi[(size_t)(k0 + kk) * GG + p0 + pp] = hi;
            dst_lo[(size_t)(k0 + kk) * GG + p0 + pp] = lo;
        }
    }
}

__global__ void prep_xA(const float* __restrict__ x) {
    size_t i4 = (size_t)blockIdx.x * blockDim.x + threadIdx.x;
    if (i4 >= (size_t)BB * SS * DD / 4) return;
    float4 v = *(const float4*)(x + i4 * 4);
    __half h0 = __float2half(v.x), h1 = __float2half(v.y);
    __half h2 = __float2half(v.z), h3 = __float2half(v.w);
    __half l0 = __float2half(v.x - __half2float(h0));
    __half l1 = __float2half(v.y - __half2float(h1));
    __half l2 = __float2half(v.z - __half2float(h2));
    __half l3 = __float2half(v.w - __half2float(h3));
    __half2 hp0 = {h0, h1}, hp1 = {h2, h3}, lp0 = {l0, l1}, lp1 = {l2, l3};
    uint2 hw = {*(u32*)&hp0, *(u32*)&hp1};
    uint2 lw = {*(u32*)&lp0, *(u32*)&lp1};
    *(uint2*)(&g_xA[0][0] + i4 * 4) = hw;
    *(uint2*)(&g_xA[1][0] + i4 * 4) = lw;
}

// ================= input GEMM: fp16 split-2, 3 products, N=128 tiles ========
// (R12-verbatim champion config: 8 warps = 8 M-groups x full-N)

#define GA_STRIDE 36864
#define GB_BASE   110592
#define GB_STRIDE 34816
#define GEMM_SMEM 215040

extern __shared__ char smx[];

__device__ __forceinline__ void g_loadA(u32 dst, int m0, int k0, int tid) {
#pragma unroll
    for (int i = 0; i < 8; i++) {
        int o = tid + i * 256;                 // 0..2047
        int row = o >> 3, seg = o & 7;
        int st = row >> 7, r = row & 127;
        int sp = r >> 6;
        int srow = m0 + st * 64 + (r & 63);
        cp_async16(dst + st * 18432 + r * 144 + seg * 16,
                   (const char*)(&g_xA[sp][0] + (size_t)srow * DD + k0) + seg * 16);
    }
}
__device__ __forceinline__ void g_loadB(u32 dst, int n0, int k0, int tid) {
#pragma unroll
    for (int i = 0; i < 8; i++) {
        int o = tid + i * 256;                 // 0..2047
        int sp = o >> 10, r = (o & 1023) >> 4, seg = o & 15;
        cp_async16(dst + sp * 17408 + r * 272 + seg * 16,
                   (const char*)(&g_WiB[sp][k0 + r][n0]) + seg * 16);
    }
}

__global__ __launch_bounds__(256, 1) void gemm_xg_mma() {
    const int tid = threadIdx.x;
    const int wid = tid >> 5, lane = tid & 31;
    const int st = wid >> 2, q = wid & 3;
    const int n0 = blockIdx.x * 128;
    const int m0 = blockIdx.y * 128;
    const u32 sb = smem_u32(smx);

    float accH0[16][4], accH1[16][4], accL[16][4];
#pragma unroll
    for (int b = 0; b < 16; b++)
#pragma unroll
        for (int c = 0; c < 4; c++) { accH0[b][c] = 0.f; accH1[b][c] = 0.f; accL[b][c] = 0.f; }

    // preload chunks 0, 1
    g_loadA(sb + 0 * GA_STRIDE, m0, 0, tid);
    g_loadB(sb + GB_BASE + 0 * GB_STRIDE, n0, 0, tid);
    cp_commit();
    g_loadA(sb + 1 * GA_STRIDE, m0, 64, tid);
    g_loadB(sb + GB_BASE + 1 * GB_STRIDE, n0, 64, tid);
    cp_commit();

    const u32 a_ro = (q * 16 + (lane & 15)) * 144 + (lane >> 4) * 16;
    const u32 b_ro = (lane & 15) * 272 + (lane >> 4) * 16;

    for (int cc = 0; cc < 16; cc++) {
        if (cc < 15) cp_wait<1>(); else cp_wait<0>();
        __syncthreads();
        if (cc < 14) {
            int nx = (cc + 2) % 3;
            g_loadA(sb + nx * GA_STRIDE, m0, (cc + 2) * 64, tid);
            g_loadB(sb + GB_BASE + nx * GB_STRIDE, n0, (cc + 2) * 64, tid);
            cp_commit();
        }

        const u32 Ab = sb + (cc % 3) * GA_STRIDE + st * 18432;
        const u32 Bb = sb + GB_BASE + (cc % 3) * GB_STRIDE;
#pragma unroll
        for (int kk = 0; kk < 4; kk++) {
            u32 a0, a1, a2, a3, a4, a5, a6, a7;
            u32 aaddr = Ab + a_ro + kk * 32;
            ldsm_x4(aaddr, a0, a1, a2, a3);               // hi rows
            ldsm_x4(aaddr + 64 * 144, a4, a5, a6, a7);    // lo rows (same real rows)
            u32 bk = Bb + b_ro + kk * 16 * 272;
#pragma unroll
            for (int n16 = 0; n16 < 8; n16++) {           // B_hi: hi + lo rows
                u32 b0, b1, b2, b3;
                ldsm_x4t(bk + n16 * 32, b0, b1, b2, b3);
                mma16816(accH0[n16 * 2], a0, a1, a2, a3, b0, b1);
                mma16816(accH0[n16 * 2 + 1], a0, a1, a2, a3, b2, b3);
                mma16816(accH1[n16 * 2], a4, a5, a6, a7, b0, b1);
                mma16816(accH1[n16 * 2 + 1], a4, a5, a6, a7, b2, b3);
            }
#pragma unroll
            for (int n16 = 0; n16 < 8; n16++) {           // B_lo (scaled), hi rows only
                u32 b0, b1, b2, b3;
                ldsm_x4t(bk + 17408 + n16 * 32, b0, b1, b2, b3);
                mma16816(accL[n16 * 2], a0, a1, a2, a3, b0, b1);
                mma16816(accL[n16 * 2 + 1], a0, a1, a2, a3, b2, b3);
            }
        }
    }

    // epilogue: all-in-register combine (hi/lo products share real rows)
    const int g = lane >> 2, tq = lane & 3;
    const int rbase = m0 + st * 64 + q * 16 + g;
#pragma unroll
    for (int nt = 0; nt < 16; nt++) {
        int c = nt * 8 + tq * 2;
        float bz0 = g_bias[n0 + c], bz1 = g_bias[n0 + c + 1];
        {
            int mg = rbase;
            float v0 = accH0[nt][0] + accH1[nt][0] + ILOSC * accL[nt][0] + bz0;
            float v1 = accH0[nt][1] + accH1[nt][1] + ILOSC * accL[nt][1] + bz1;
            int bb = mg >> 9, tt = mg & 511;
            *(float2*)&g_xg[((size_t)tt * BB + bb) * GG + n0 + c] = make_float2(v0, v1);
        }
        {
            int mg = rbase + 8;
            float v0 = accH0[nt][2] + accH1[nt][2] + ILOSC * accL[nt][2] + bz0;
            float v1 = accH0[nt][3] + accH1[nt][3] + ILOSC * accL[nt][3] + bz1;
            int bb = mg >> 9, tt = mg & 511;
            *(float2*)&g_xg[((size_t)tt * BB + bb) * GG + n0 + c] = make_float2(v0, v1);
        }
    }
}

// ================= persistent recurrent kernel (R12 protocol, verbatim) =====

#define PB 0
#define PA_BASE 163840
#define PA_STRIDE 18432
#define PXG 219136
#define PERSIST_SMEM 227328

__device__ __forceinline__ void p_loadA(u32 dst, const __half* hA, int k0, int tid) {
#pragma unroll
    for (int i = 0; i < 4; i++) {
        int o = tid + i * 256;
        int row = o >> 3, seg = o & 7;
        cp_async16_cg(dst + row * 144 + seg * 16,
                      (const char*)(hA + (size_t)row * HH + k0) + seg * 16);
    }
}

__device__ __forceinline__ void wait_step(u32 target, int tid) {
    bool ok = true;
    if (tid < 16) ok = (ld_acq(&g_flags[tid]) >= target);
    while (!__syncthreads_and(ok)) {
        __nanosleep(40);
        if (tid < 16) ok = (ld_acq(&g_flags[tid]) >= target);
    }
}

__global__ __launch_bounds__(256, 1) void lstm_persist(float* __restrict__ out) {
    const int tid = threadIdx.x;
    const int wid = tid >> 5, lane = tid & 31;
    const int wm = wid & 3, wn = wid >> 2;
    const int s = blockIdx.x;
    const int c0 = s * 32;
    const int j0 = s * 8;
    const u32 sb = smem_u32(smx);
    float* xs = (float*)(smx + PXG);

    // ---- resident Wh tiles (hi at +0, lo-scaled at +81920), 80B rows ----
#pragma unroll
    for (int i = 0; i < 32; i++) {
        int o = tid + i * 256;
        int sp = o >> 12;
        int rem = o & 4095;
        int k = rem >> 2, seg = rem & 3;
        cp_async16(sb + PB + sp * 81920 + k * 80 + seg * 16,
                   (const char*)(&g_WhB[sp][k][c0]) + seg * 16);
    }
    cp_commit();
    cp_wait<0>();
    __syncthreads();

    // lane cell mapping
    const int g = lane >> 2, tq = lane & 3;
    const int brow = wm * 16 + g + ((tq & 1) ? 8 : 0);
    const int u0 = wn * 4 + (tq >> 1);
    float cr[2];
#pragma unroll
    for (int nt = 0; nt < 2; nt++) cr[nt] = g_cbuf[(size_t)brow * HH + j0 + u0 + nt * 2];

    const u32 a_ro = (wm * 16 + (lane & 15)) * 144 + (lane >> 4) * 16;
    const u32 b_cb = (wn * 16 + (lane >> 4) * 8) * 2;
    const u32 bufs[3] = {sb + PA_BASE, sb + PA_BASE + PA_STRIDE, sb + PA_BASE + 2 * PA_STRIDE};

    for (int t = 0; t < SS; t++) {
        const int ping = t & 1;
        const __half* hA = &g_hA[ping][0][0];

        wait_step(8u * (u32)t, tid);

        float p0[2][4], p1[2][4], p2[2][4];
#pragma unroll
        for (int nt = 0; nt < 2; nt++)
#pragma unroll
            for (int qq = 0; qq < 4; qq++) { p0[nt][qq] = 0.f; p1[nt][qq] = 0.f; p2[nt][qq] = 0.f; }

        // xs prefetch + chunk 0 in one commit group; chunk 1 second group
#pragma unroll
        for (int i = 0; i < 2; i++) {
            int o = tid + i * 256;
            int b = o >> 3, seg = o & 7;
            cp_async16(sb + PXG + b * 128 + seg * 16,
                       (const char*)(g_xg + ((size_t)t * BB + b) * GG + c0) + seg * 16);
        }
        p_loadA(bufs[0], hA, 0, tid);
        cp_commit();
        p_loadA(bufs[1], hA, 64, tid);
        cp_commit();

        for (int cc = 0; cc < 16; cc++) {
            if (cc < 15) cp_wait<1>(); else cp_wait<0>();
            __syncthreads();
            if (cc < 14) {
                p_loadA(bufs[(cc + 2) % 3], hA, (cc + 2) * 64, tid);
                cp_commit();
            }

            const u32 Ab = bufs[cc % 3];
#pragma unroll
            for (int kk = 0; kk < 4; kk++) {
                u32 a0, a1, a2, a3, a4, a5, a6, a7;
                u32 aaddr = Ab + a_ro + kk * 32;
                ldsm_x4(aaddr, a0, a1, a2, a3);                // h_hi rows
                ldsm_x4(aaddr + 64 * 144, a4, a5, a6, a7);     // h_lo rows
                u32 b0, b1, b2, b3, b4, b5, b6, b7;
                u32 baddr = sb + PB + (cc * 64 + kk * 16 + (lane & 15)) * 80 + b_cb;
                ldsm_x4t(baddr, b0, b1, b2, b3);               // W_hi
                ldsm_x4t(baddr + 81920, b4, b5, b6, b7);       // W_lo*2048
                mma16816(p0[0], a0, a1, a2, a3, b0, b1);
                mma16816(p0[1], a0, a1, a2, a3, b2, b3);
                mma16816(p1[0], a4, a5, a6, a7, b0, b1);
                mma16816(p1[1], a4, a5, a6, a7, b2, b3);
                mma16816(p2[0], a0, a1, a2, a3, b4, b5);
                mma16816(p2[1], a0, a1, a2, a3, b6, b7);
            }
        }

        // in-register gate combine + xs
        float hv[2];
        u32 hiw[2], low[2];
#pragma unroll
        for (int nt = 0; nt < 2; nt++) {
            float q0 = p0[nt][0] + p1[nt][0] + ILOSC * p2[nt][0];
            float q1 = p0[nt][1] + p1[nt][1] + ILOSC * p2[nt][1];
            float q2 = p0[nt][2] + p1[nt][2] + ILOSC * p2[nt][2];
            float q3 = p0[nt][3] + p1[nt][3] + ILOSC * p2[nt][3];
            int b0r = wm * 16 + g;
            int col = wn * 16 + nt * 8 + tq * 2;
            q0 += xs[b0r * 32 + col];       q1 += xs[b0r * 32 + col + 1];
            q2 += xs[(b0r + 8) * 32 + col]; q3 += xs[(b0r + 8) * 32 + col + 1];
            float r0 = __shfl_xor_sync(0xFFFFFFFFu, q0, 1);
            float r1 = __shfl_xor_sync(0xFFFFFFFFu, q1, 1);
            float r2 = __shfl_xor_sync(0xFFFFFFFFu, q2, 1);
            float r3 = __shfl_xor_sync(0xFFFFFFFFu, q3, 1);
            float gi, gf, gg, go;
            if ((tq & 1) == 0) { gi = q0; gf = q1; gg = r0; go = r1; }
            else               { gi = r2; gf = r3; gg = q2; go = q3; }
            float c = sigf(gf) * cr[nt] + sigf(gi) * tanhf(gg);
            cr[nt] = c;
            float h = sigf(go) * tanhf(c);
            hv[nt] = h;
            __half hi = __float2half(h);
            __half lo = __float2half(h - __half2float(hi));
            hiw[nt] = *(unsigned short*)&hi;
            low[nt] = *(unsigned short*)&lo;
        }
        // next-step h tiles first (they gate other CTAs)
#pragma unroll
        for (int nt = 0; nt < 2; nt++) {
            int j = j0 + u0 + nt * 2;
            *(unsigned short*)&g_hA[ping ^ 1][brow][j] = (unsigned short)hiw[nt];
            *(unsigned short*)&g_hA[ping ^ 1][brow + 64][j] = (unsigned short)low[nt];
        }
        __syncthreads();
        if (tid == 0) red_release(&g_flags[s >> 3]);
        // out stores off the critical path
#pragma unroll
        for (int nt = 0; nt < 2; nt++)
            out[((size_t)brow * SS + t) * HH + j0 + u0 + nt * 2] = hv[nt];
    }

#pragma unroll
    for (int nt = 0; nt < 2; nt++)
        g_cbuf[(size_t)brow * HH + j0 + u0 + nt * 2] = cr[nt];
}

// ================= tail =================
__global__ void write_tail(float* __restrict__ out, long long hsz, int want_c) {
    int i = blockIdx.x * blockDim.x + threadIdx.x;
    if (i < BB * HH) {
        int b = i / HH, j = i % HH;
        out[hsz + i] = out[((size_t)b * SS + (SS - 1)) * HH + j];
        if (want_c) out[hsz + (long long)BB * HH + i] = g_cbuf[i];
    }
}

// ================= launch =================
extern "C" void kernel_launch(void* const* d_in, const int* in_sizes, int n_in,
                              void* d_out, int out_size) {
    const float* x  = (const float*)d_in[0];
    const float* h0 = (const float*)d_in[1];
    const float* c0 = (const float*)d_in[2];
    const float* Wi = (const float*)d_in[3];
    const float* bi = (const float*)d_in[4];
    const float* Wh = (const float*)d_in[5];
    const float* bh = (const float*)d_in[6];
    float* out = (float*)d_out;

    cudaFuncSetAttribute(gemm_xg_mma, cudaFuncAttributeMaxDynamicSharedMemorySize, GEMM_SMEM);
    cudaFuncSetAttribute(lstm_persist, cudaFuncAttributeMaxDynamicSharedMemorySize, PERSIST_SMEM);

    init_state<<<(BB * HH + 255) / 256, 256>>>(h0, c0, bi, bh);
    init_hA<<<(BB * HH + 255) / 256, 256>>>(h0);

    dim3 gw(GG / 32, 32);   // 32 k-tiles of 32 (K=1024)
    prep_w<<<gw, 256>>>(Wh, 0);
    prep_w<<<gw, 256>>>(Wi, 1);
    prep_xA<<<(int)(((size_t)BB * SS * DD / 4) / 256), 256>>>(x);

    dim3 gg(GG / 128, (BB * SS) / 128);
    gemm_xg_mma<<<gg, 256, GEMM_SMEM>>>();

    lstm_persist<<<128, 256, PERSIST_SMEM>>>(out);

    long long hsz = (long long)BB * SS * HH;
    int want_h = ((long long)out_size >= hsz + (long long)BB * HH) ? 1 : 0;
    int want_c = ((long long)out_size >= hsz + 2LL * BB * HH) ? 1 : 0;
    if (want_h) {
        write_tail<<<(BB * HH + 255) / 256, 256>>>(out, hsz, want_c);
    }
}